// round 11
// baseline (speedup 1.0000x reference)
#include <cuda_runtime.h>
#include <cuda_fp16.h>
#include <cstdint>

#define B    8
#define S    1024
#define D    96
#define G    8
#define MTOT (D*D)          // 9216
#define ND   (B*D)          // 768
#define DPAD 100
#define LN_EPS 1e-5f
#define TWO_PI 6.283185307179586f

// ---------------- scratch (device globals; no allocation allowed) ----------
__device__ __half g_W   [S*MTOT];      // W[s, i*96+j] fp16            (18 MB)
__device__ float  g_A   [S*ND];        // (T+Z0) as A[s, b*96+i]       (3 MB)
__device__ float  g_part[4*S*ND];      // split-K partials             (12.6 MB)
__device__ int    g_cnt [16*6];        // per-tile arrival counters (self-resetting)

// ---------------- packed f32x2 helpers (sm_103) -----------------------------
__device__ __forceinline__ unsigned long long splat2(float a) {
    unsigned long long r;
    asm("mov.b64 %0, {%1, %1};" : "=l"(r) : "f"(a));
    return r;
}
__device__ __forceinline__ void fma2(unsigned long long& d,
                                     unsigned long long a,
                                     unsigned long long b) {
    asm("fma.rn.f32x2 %0, %1, %2, %0;" : "+l"(d) : "l"(a), "l"(b));
}
__device__ __forceinline__ float2 unpack2(unsigned long long v) {
    float lo, hi;
    asm("mov.b64 {%0, %1}, %2;" : "=f"(lo), "=f"(hi) : "l"(v));
    return make_float2(lo, hi);
}

// ---------------- K2: W[s,m] = sum_g P[m*8+g] * cos(2*pi*s/(8m+g+2)) -------
#define SCHUNK 64
__global__ void k2_basis(const float* __restrict__ P)
{
    const int gidx  = blockIdx.x*blockDim.x + threadIdx.x;
    const int m     = gidx % MTOT;
    const int chunk = gidx / MTOT;
    const int s0    = chunk * SCHUNK;

    float kg[G], c0[G], c1[G], Pv[G];
#pragma unroll
    for (int g = 0; g < G; ++g) {
        const int p    = m*G + g + 2;
        const float fp = (float)p;
        kg[g] = 2.f * cosf(TWO_PI / fp);
        const int r0  = s0 % p;
        const int rm1 = (s0 + p - 1) % p;
        c1[g] = cosf(TWO_PI * (float)r0  / fp);
        c0[g] = cosf(TWO_PI * (float)rm1 / fp);
        Pv[g] = P[m*G + g];
    }

    __half* Wp = g_W + (size_t)s0*MTOT + m;
    for (int s = 0; s < SCHUNK; ++s) {
        float w = 0.f;
#pragma unroll
        for (int g = 0; g < G; ++g) w = fmaf(Pv[g], c1[g], w);
        Wp[(size_t)s*MTOT] = __float2half(w);
#pragma unroll
        for (int g = 0; g < G; ++g) {
            const float cn = fmaf(kg[g], c1[g], -c0[g]);
            c0[g] = c1[g];
            c1[g] = cn;
        }
    }
}

// ---------------- K13: fused project + LN + per-s mixing + residual --------
__global__ __launch_bounds__(768) void k13_fused(const float* __restrict__ x,
                                                 const float* __restrict__ M,
                                                 const float* __restrict__ gamma,
                                                 const float* __restrict__ beta)
{
    const int s   = blockIdx.x;
    const int tid = threadIdx.x;
    const int i   = tid >> 3;          // 0..95
    const int b   = tid & 7;           // 0..7

    __shared__ __align__(16) float sBuf[D*DPAD];
    __shared__ __align__(16) float sx  [B*DPAD];
    __shared__ __align__(16) float sZ  [B*DPAD];
    __shared__ float sS1[24][8], sS2[24][8];

    __half2 wreg[6];
    const __half2* Wp = reinterpret_cast<const __half2*>(g_W + (size_t)s*MTOT);
#pragma unroll
    for (int r = 0; r < 6; ++r) wreg[r] = Wp[tid + r*768];

    {
        const int bb = tid / D, jj = tid % D;
        sx[bb*DPAD + jj] = x[((size_t)bb*S + s)*D + jj];
    }
#pragma unroll
    for (int r = 0; r < 12; ++r) {
        const int f = tid + r*768;
        sBuf[(f / D)*DPAD + (f % D)] = M[f];
    }
    __syncthreads();

    float z0 = 0.f;
    {
        const float4* mr = reinterpret_cast<const float4*>(sBuf + i*DPAD);
        const float4* xr = reinterpret_cast<const float4*>(sx + b*DPAD);
#pragma unroll
        for (int j4 = 0; j4 < D/4; ++j4) {
            const float4 m4 = mr[j4];
            const float4 x4 = xr[j4];
            z0 = fmaf(m4.x, x4.x, z0);
            z0 = fmaf(m4.y, x4.y, z0);
            z0 = fmaf(m4.z, x4.z, z0);
            z0 = fmaf(m4.w, x4.w, z0);
        }
    }

    float s1 = z0, s2 = z0*z0;
    s1 += __shfl_xor_sync(0xffffffffu, s1, 8);
    s2 += __shfl_xor_sync(0xffffffffu, s2, 8);
    s1 += __shfl_xor_sync(0xffffffffu, s1, 16);
    s2 += __shfl_xor_sync(0xffffffffu, s2, 16);
    const int w = tid >> 5, lane = tid & 31;
    if (lane < 8) { sS1[w][lane] = s1; sS2[w][lane] = s2; }
    __syncthreads();
    float t1 = 0.f, t2 = 0.f;
#pragma unroll
    for (int ww = 0; ww < 24; ++ww) { t1 += sS1[ww][b]; t2 += sS2[ww][b]; }
    const float mu  = t1 * (1.f/D);
    const float rstd = rsqrtf(t2 * (1.f/D) - mu*mu + LN_EPS);
    sZ[b*DPAD + i] = (z0 - mu)*rstd*gamma[i] + beta[i];

#pragma unroll
    for (int r = 0; r < 6; ++r) {
        const int e0  = 2*(tid + r*768);
        const int row = e0 / D, col = e0 % D;
        const float2 v = __half22float2(wreg[r]);
        sBuf[row*DPAD + col]     = v.x;
        sBuf[row*DPAD + col + 1] = v.y;
    }
    __syncthreads();

    float acc = 0.f;
    {
        const float4* wr = reinterpret_cast<const float4*>(sBuf + i*DPAD);
        const float4* zr = reinterpret_cast<const float4*>(sZ + b*DPAD);
#pragma unroll
        for (int j4 = 0; j4 < D/4; ++j4) {
            const float4 w4 = wr[j4];
            const float4 z4 = zr[j4];
            acc = fmaf(w4.x, z4.x, acc);
            acc = fmaf(w4.y, z4.y, acc);
            acc = fmaf(w4.z, z4.z, acc);
            acc = fmaf(w4.w, z4.w, acc);
        }
    }
    g_A[(size_t)s*ND + b*D + i] = acc + z0;
}

// ---------------- K4: split-K GEMM, 64x128 tile, broadcast micro, fused reduce
// warp = 8 t-rows (broadcast L) x 128 n; lane owns 4 n columns.
#define BT 64
#define BN 128
#define BK 16
#define KSPLIT 4
#define KCH (S/KSPLIT)     // 256
#define NIT (KCH/BK)       // 16
__global__ __launch_bounds__(256) void k4_gemm(const float* __restrict__ L,
                                               float* __restrict__ out)
{
    __shared__ __align__(16) float Ls[2][BK][BT];   // 2 * 4 KB
    __shared__ __align__(16) float As[2][BK][BN];   // 2 * 8 KB
    __shared__ int sIsLast;
    const int tid = threadIdx.x;
    const int w   = tid >> 5;          // warp: t-block
    const int l   = tid & 31;          // lane: 4 n cols
    const int n0  = blockIdx.x * BN;
    const int t0  = blockIdx.y * BT;
    const int z   = blockIdx.z;
    const int kbeg = z * KCH;

    // loader indices: Ls 1 float4/thread, As 2 float4/thread
    const int lkk = tid >> 4, lc = (tid & 15) * 4;   // Ls[kk][lc..+3]
    const int akk = tid >> 4, ac = (tid & 15) * 8;   // As[kk][ac..+7]

    unsigned long long acc2[4][4];     // [t-pair u][n v]
#pragma unroll
    for (int u = 0; u < 4; ++u)
#pragma unroll
        for (int v = 0; v < 4; ++v) acc2[u][v] = 0ull;

    float4 pL, pA0, pA1;
    pL  = *reinterpret_cast<const float4*>(&L[(size_t)(kbeg+lkk)*S + t0 + lc]);
    pA0 = *reinterpret_cast<const float4*>(&g_A[(size_t)(kbeg+akk)*ND + n0 + ac]);
    pA1 = *reinterpret_cast<const float4*>(&g_A[(size_t)(kbeg+akk)*ND + n0 + ac + 4]);
    *reinterpret_cast<float4*>(&Ls[0][lkk][lc])     = pL;
    *reinterpret_cast<float4*>(&As[0][akk][ac])     = pA0;
    *reinterpret_cast<float4*>(&As[0][akk][ac + 4]) = pA1;
    __syncthreads();

    for (int it = 0; it < NIT; ++it) {
        const int cur = it & 1;
        if (it + 1 < NIT) {
            const int ks = kbeg + (it+1)*BK;
            pL  = *reinterpret_cast<const float4*>(&L[(size_t)(ks+lkk)*S + t0 + lc]);
            pA0 = *reinterpret_cast<const float4*>(&g_A[(size_t)(ks+akk)*ND + n0 + ac]);
            pA1 = *reinterpret_cast<const float4*>(&g_A[(size_t)(ks+akk)*ND + n0 + ac + 4]);
        }
#pragma unroll
        for (int kk = 0; kk < BK; ++kk) {
            // L fragment: 8 t values shared by all lanes (smem broadcast)
            const ulonglong2 lq0 =
                *reinterpret_cast<const ulonglong2*>(&Ls[cur][kk][w*8]);
            const ulonglong2 lq1 =
                *reinterpret_cast<const ulonglong2*>(&Ls[cur][kk][w*8 + 4]);
            const unsigned long long lp[4] = {lq0.x, lq0.y, lq1.x, lq1.y};
            // A fragment: 4 distinct n per lane
            const float4 a4 = *reinterpret_cast<const float4*>(&As[cur][kk][l*4]);
            const unsigned long long ap[4] =
                {splat2(a4.x), splat2(a4.y), splat2(a4.z), splat2(a4.w)};
#pragma unroll
            for (int u = 0; u < 4; ++u)
#pragma unroll
                for (int v = 0; v < 4; ++v)
                    fma2(acc2[u][v], lp[u], ap[v]);
        }
        if (it + 1 < NIT) {
            const int nxt = cur ^ 1;
            *reinterpret_cast<float4*>(&Ls[nxt][lkk][lc])     = pL;
            *reinterpret_cast<float4*>(&As[nxt][akk][ac])     = pA0;
            *reinterpret_cast<float4*>(&As[nxt][akk][ac + 4]) = pA1;
        }
        __syncthreads();
    }

    // ---- write this split's partial tile ----
    float* base = g_part + (size_t)z*(S*ND);
#pragma unroll
    for (int u = 0; u < 4; ++u) {
        float2 r0 = unpack2(acc2[u][0]);
        float2 r1 = unpack2(acc2[u][1]);
        float2 r2 = unpack2(acc2[u][2]);
        float2 r3 = unpack2(acc2[u][3]);
        const int t = t0 + w*8 + 2*u;
        *reinterpret_cast<float4*>(base + (size_t)t*ND + n0 + l*4) =
            make_float4(r0.x, r1.x, r2.x, r3.x);
        *reinterpret_cast<float4*>(base + (size_t)(t+1)*ND + n0 + l*4) =
            make_float4(r0.y, r1.y, r2.y, r3.y);
    }
    __syncthreads();

    // ---- arrival counter: last CTA of the 4 splits reduces (fixed z order,
    //      so the result is bitwise-deterministic regardless of arrival order)
    const int tile = blockIdx.y * gridDim.x + blockIdx.x;
    if (tid == 0) {
        __threadfence();
        const int old = atomicAdd(&g_cnt[tile], 1);
        sIsLast = (old == KSPLIT - 1);
        if (old == KSPLIT - 1) g_cnt[tile] = 0;    // self-reset for graph replay
    }
    __syncthreads();

    if (sIsLast) {
        __threadfence();                           // acquire all partials
#pragma unroll
        for (int q = 0; q < 8; ++q) {              // 64x128 tile = 2048 float4
            const int idx  = tid + q*256;
            const int row  = idx >> 5;             // t-local
            const int col4 = (idx & 31) * 4;       // n-local
            const size_t off = ((size_t)(t0 + row)*ND + n0 + col4) / 4;
            const float4* p0 = reinterpret_cast<const float4*>(g_part) + off;
            const size_t step = (size_t)(S*ND)/4;
            float4 a = p0[0];
#pragma unroll
            for (int zz = 1; zz < KSPLIT; ++zz) {
                const float4 qv = p0[zz*step];
                a.x += qv.x; a.y += qv.y; a.z += qv.z; a.w += qv.w;
            }
            const int n  = n0 + col4;
            const int bb = n / D, ii = n - bb*D;   // 4-group never straddles b
            *reinterpret_cast<float4*>(out + (size_t)bb*(S*D)
                                           + (size_t)(t0 + row)*D + ii) = a;
        }
    }
}

// ---------------- launch ----------------------------------------------------
extern "C" void kernel_launch(void* const* d_in, const int* in_sizes, int n_in,
                              void* d_out, int out_size)
{
    const float* x     = (const float*)d_in[0];   // (8,1024,96)
    const float* M     = (const float*)d_in[1];   // (96,96)
    const float* P     = (const float*)d_in[2];   // (96,96,8)
    const float* L     = (const float*)d_in[3];   // (1024,1024)
    const float* gamma = (const float*)d_in[4];   // (96)
    const float* beta  = (const float*)d_in[5];   // (96)
    float* out = (float*)d_out;                   // (8,1024,96)

    k2_basis <<<(MTOT*(S/SCHUNK))/256, 256>>>(P);            // 576 blocks
    k13_fused<<<S, 768>>>(x, M, gamma, beta);                // 1024 blocks
    k4_gemm  <<<dim3(ND/BN, S/BT, KSPLIT), 256>>>(L, out);   // 384 blocks
}